// round 2
// baseline (speedup 1.0000x reference)
#include <cuda_runtime.h>
#include <math.h>

#define NS 16      // states
#define NN 5000    // nodes
#define NC 8       // chains
#define NT 100     // iters

// Scratch (allocation-free rule: __device__ globals)
__device__ float g_h[NT * NS];      // log hidden state probs
__device__ float g_H[NT * NS];      // exp(log hidden state probs)
__device__ float g_em_lse[NS];      // per-state logsumexp over nodes
__device__ float g_cw_lse[NN];      // per-node logsumexp over chains

// ---------------------------------------------------------------------------
// Kernel 1: scalars + HMM recursion. One block, 512 threads (16 warps).
//   warp w  -> em_lse[w] (lse over 5000 nodes of emission row w)
//   tid<16  -> logT row normalization
//   tid==0  -> log_state_init
//   warp 0  -> serial T=100 recursion, writes hidden output + g_h/g_H
// ---------------------------------------------------------------------------
__global__ void prep_kernel(const float* __restrict__ usi,
                            const float* __restrict__ uem,
                            const float* __restrict__ utr,
                            float* __restrict__ out_hidden) {
    __shared__ float sh_logT[NS][NS];
    __shared__ float sh_h[NS];

    const int tid  = threadIdx.x;
    const int wid  = tid >> 5;
    const int lane = tid & 31;

    // --- per-state emission lse (warp wid handles state wid) ---
    {
        const float* row = uem + wid * NN;
        float m = -3.402823466e38f;
        for (int i = lane; i < NN; i += 32) m = fmaxf(m, row[i]);
        #pragma unroll
        for (int o = 16; o; o >>= 1) m = fmaxf(m, __shfl_xor_sync(0xffffffffu, m, o));
        float s = 0.f;
        for (int i = lane; i < NN; i += 32) s += expf(row[i] - m);
        #pragma unroll
        for (int o = 16; o; o >>= 1) s += __shfl_xor_sync(0xffffffffu, s, o);
        if (lane == 0) g_em_lse[wid] = m + logf(s);
    }

    // --- transition row log-softmax (threads 0..15, one row each) ---
    if (tid < NS) {
        float m = -3.402823466e38f;
        #pragma unroll
        for (int j = 0; j < NS; j++) m = fmaxf(m, utr[tid * NS + j]);
        float s = 0.f;
        #pragma unroll
        for (int j = 0; j < NS; j++) s += expf(utr[tid * NS + j] - m);
        const float lse = m + logf(s);
        #pragma unroll
        for (int j = 0; j < NS; j++) sh_logT[tid][j] = utr[tid * NS + j] - lse;
    }

    // --- initial state log-softmax ---
    if (tid == 0) {
        float m = -3.402823466e38f;
        #pragma unroll
        for (int j = 0; j < NS; j++) m = fmaxf(m, usi[j]);
        float s = 0.f;
        #pragma unroll
        for (int j = 0; j < NS; j++) s += expf(usi[j] - m);
        const float lse = m + logf(s);
        #pragma unroll
        for (int j = 0; j < NS; j++) sh_h[j] = usi[j] - lse;
    }
    __syncthreads();

    // --- serial recursion on warp 0 (all 32 lanes execute; lanes>=16 mirror) ---
    if (wid == 0) {
        const int j = lane & (NS - 1);
        float lT[NS];
        #pragma unroll
        for (int i = 0; i < NS; i++) lT[i] = sh_logT[i][j];

        if (lane < NS) {
            const float h0 = sh_h[j];
            g_h[j] = h0; g_H[j] = expf(h0); out_hidden[j] = h0;
        }
        for (int t = 1; t < NT; t++) {
            float m = -3.402823466e38f;
            #pragma unroll
            for (int i = 0; i < NS; i++) m = fmaxf(m, sh_h[i] + lT[i]);
            float s = 0.f;
            #pragma unroll
            for (int i = 0; i < NS; i++) s += expf(sh_h[i] + lT[i] - m);
            const float hn = m + logf(s);
            __syncwarp();
            if (lane < NS) sh_h[j] = hn;
            __syncwarp();
            if (lane < NS) {
                g_h[t * NS + j] = hn;
                g_H[t * NS + j] = expf(hn);
                out_hidden[t * NS + j] = hn;
            }
        }
    }
}

// ---------------------------------------------------------------------------
// Kernel 2: per-node chain-weight lse (8 values each)
// ---------------------------------------------------------------------------
__global__ void cw_kernel(const float* __restrict__ ucw) {
    const int n = blockIdx.x * blockDim.x + threadIdx.x;
    if (n >= NN) return;
    const float4 a = reinterpret_cast<const float4*>(ucw)[n * 2 + 0];
    const float4 b = reinterpret_cast<const float4*>(ucw)[n * 2 + 1];
    float m = fmaxf(fmaxf(fmaxf(a.x, a.y), fmaxf(a.z, a.w)),
                    fmaxf(fmaxf(b.x, b.y), fmaxf(b.z, b.w)));
    float s = expf(a.x - m) + expf(a.y - m) + expf(a.z - m) + expf(a.w - m)
            + expf(b.x - m) + expf(b.y - m) + expf(b.z - m) + expf(b.w - m);
    g_cw_lse[n] = m + logf(s);
}

// ---------------------------------------------------------------------------
// Kernel 3: out1[t,n] = log( sum_s exp(log_em[s,n]) * exp(h[t,s]) )
// (chain softmax sums to 1, so it drops out of the joint lse over (s,c))
// ---------------------------------------------------------------------------
__global__ void obs_kernel(const float* __restrict__ uem,
                           float* __restrict__ out1) {
    __shared__ float sH[NT * NS];
    const int tid = threadIdx.x;
    for (int i = tid; i < NT * NS; i += blockDim.x) sH[i] = g_H[i];
    __syncthreads();

    const int n = blockIdx.x * blockDim.x + tid;
    if (n >= NN) return;

    float P[NS];
    #pragma unroll
    for (int s = 0; s < NS; s++) P[s] = expf(uem[s * NN + n] - g_em_lse[s]);

    for (int t = 0; t < NT; t++) {
        float acc = 0.f;
        #pragma unroll
        for (int s = 0; s < NS; s++) acc += P[s] * sH[t * NS + s];
        out1[t * NN + n] = logf(acc);
    }
}

// ---------------------------------------------------------------------------
// Kernel 4: the 256 MB broadcast writer.
// perm[t,s,c,n] = (em[s,n]-em_lse[s]) + (cw[n,c]-cw_lse[n]) + h[t,s]
// grid: x over 1250 float4 positions of an n-row, y over 128 (s,c) pairs.
// Each thread: one float4 base, 100 coalesced STG.128 across t-planes.
// ---------------------------------------------------------------------------
__global__ void perm_kernel(const float* __restrict__ uem,
                            const float* __restrict__ ucw,
                            float* __restrict__ outp) {
    __shared__ float sh[NT];
    const int by = blockIdx.y;        // s*8 + c
    const int s  = by >> 3;
    const int c  = by & 7;
    const int tid = threadIdx.x;

    for (int i = tid; i < NT; i += blockDim.x) sh[i] = g_h[i * NS + s];
    __syncthreads();

    const int q = blockIdx.x * blockDim.x + tid;   // float4 index in row
    if (q >= NN / 4) return;
    const int n0 = q * 4;

    const float4 em  = *reinterpret_cast<const float4*>(uem + s * NN + n0);
    const float4 cwl = *reinterpret_cast<const float4*>(g_cw_lse + n0);
    const float  el  = g_em_lse[s];

    float4 base;
    base.x = em.x - el + ucw[(n0 + 0) * NC + c] - cwl.x;
    base.y = em.y - el + ucw[(n0 + 1) * NC + c] - cwl.y;
    base.z = em.z - el + ucw[(n0 + 2) * NC + c] - cwl.z;
    base.w = em.w - el + ucw[(n0 + 3) * NC + c] - cwl.w;

    float* ptr = outp + (size_t)by * NN + n0;
    #pragma unroll 4
    for (int t = 0; t < NT; t++) {
        const float hv = sh[t];
        float4 v;
        v.x = base.x + hv; v.y = base.y + hv; v.z = base.z + hv; v.w = base.w + hv;
        *reinterpret_cast<float4*>(ptr) = v;
        ptr += NS * NC * NN;           // next t-plane
    }
}

// ---------------------------------------------------------------------------
// Launch
// ---------------------------------------------------------------------------
extern "C" void kernel_launch(void* const* d_in, const int* in_sizes, int n_in,
                              void* d_out, int out_size) {
    const float* usi = (const float*)d_in[0];   // (16,)
    const float* ucw = (const float*)d_in[1];   // (1,5000,8)
    const float* uem = (const float*)d_in[2];   // (16,5000)
    const float* utr = (const float*)d_in[3];   // (16,16)

    float* out = (float*)d_out;
    float* out1    = out;                                   // (100,5000)
    float* outperm = out + (size_t)NT * NN;                 // (100,16,8,5000)
    float* outhid  = outperm + (size_t)NT * NS * NC * NN;   // (100,16)

    prep_kernel<<<1, 512>>>(usi, uem, utr, outhid);
    cw_kernel<<<(NN + 255) / 256, 256>>>(ucw);
    obs_kernel<<<(NN + 255) / 256, 256>>>(uem, out1);
    perm_kernel<<<dim3((NN / 4 + 255) / 256, NS * NC), 256>>>(uem, ucw, outperm);
}

// round 4
// speedup vs baseline: 1.6531x; 1.6531x over previous
#include <cuda_runtime.h>
#include <math.h>

#define NS 16      // states
#define NN 5000    // nodes
#define NC 8       // chains
#define NT 100     // iters

// Scratch (allocation-free rule: __device__ globals)
__device__ float g_h[NT * NS];      // log hidden state probs
__device__ float g_H[NT * NS];      // exp(log hidden state probs)
__device__ float g_em_lse[NS];      // per-state logsumexp over nodes
__device__ float g_cw_lse[NN];      // per-node logsumexp over chains

// ---------------------------------------------------------------------------
// Kernel 1: normalizations + HMM recursion (probability space). 1 block x 512.
//   warp w  -> em_lse[w] over 5000 nodes
//   tid<16  -> transition row softmax -> P (prob space, shared)
//   tid==0  -> initial state softmax
//   warp 0  -> serial T=100 matvec recursion H_t = H_{t-1} P (16 FFMA/step)
//   all 512 -> logs of the 1600 H values + global writes
// ---------------------------------------------------------------------------
__global__ void prep_kernel(const float* __restrict__ usi,
                            const float* __restrict__ uem,
                            const float* __restrict__ utr,
                            float* __restrict__ out_hidden) {
    __shared__ float sh_P[NS][NS + 1];   // P[i][j] = exp(logT[i][j])
    __shared__ float sh_H[NT * NS];      // prob-space hidden marginals

    const int tid  = threadIdx.x;
    const int wid  = tid >> 5;
    const int lane = tid & 31;

    // --- per-state emission lse (warp wid handles state wid) ---
    {
        const float* row = uem + wid * NN;
        float m = -3.402823466e38f;
        for (int i = lane; i < NN; i += 32) m = fmaxf(m, row[i]);
        #pragma unroll
        for (int o = 16; o; o >>= 1) m = fmaxf(m, __shfl_xor_sync(0xffffffffu, m, o));
        float s = 0.f;
        for (int i = lane; i < NN; i += 32) s += expf(row[i] - m);
        #pragma unroll
        for (int o = 16; o; o >>= 1) s += __shfl_xor_sync(0xffffffffu, s, o);
        if (lane == 0) g_em_lse[wid] = m + logf(s);
    }

    // --- transition row softmax in probability space (threads 0..15) ---
    if (tid < NS) {
        float m = -3.402823466e38f;
        #pragma unroll
        for (int j = 0; j < NS; j++) m = fmaxf(m, utr[tid * NS + j]);
        float s = 0.f;
        float e[NS];
        #pragma unroll
        for (int j = 0; j < NS; j++) { e[j] = expf(utr[tid * NS + j] - m); s += e[j]; }
        const float inv = 1.0f / s;
        #pragma unroll
        for (int j = 0; j < NS; j++) sh_P[tid][j] = e[j] * inv;
    }

    // --- initial state softmax -> sh_H row 0 ---
    if (tid == 0) {
        float m = -3.402823466e38f;
        #pragma unroll
        for (int j = 0; j < NS; j++) m = fmaxf(m, usi[j]);
        float s = 0.f;
        float e[NS];
        #pragma unroll
        for (int j = 0; j < NS; j++) { e[j] = expf(usi[j] - m); s += e[j]; }
        const float inv = 1.0f / s;
        #pragma unroll
        for (int j = 0; j < NS; j++) sh_H[j] = e[j] * inv;
    }
    __syncthreads();

    // --- serial recursion, warp 0: H_t[j] = sum_i H_{t-1}[i] * P[i][j] ---
    if (wid == 0) {
        const int j = lane & (NS - 1);
        float Pc[NS];
        #pragma unroll
        for (int i = 0; i < NS; i++) Pc[i] = sh_P[i][j];

        for (int t = 1; t < NT; t++) {
            const float* Hp = sh_H + (t - 1) * NS;
            float a0 = 0.f, a1 = 0.f, a2 = 0.f, a3 = 0.f;
            #pragma unroll
            for (int i = 0; i < 4; i++) {
                a0 = fmaf(Hp[i +  0], Pc[i +  0], a0);
                a1 = fmaf(Hp[i +  4], Pc[i +  4], a1);
                a2 = fmaf(Hp[i +  8], Pc[i +  8], a2);
                a3 = fmaf(Hp[i + 12], Pc[i + 12], a3);
            }
            const float v = (a0 + a1) + (a2 + a3);
            __syncwarp();
            if (lane < NS) sh_H[t * NS + j] = v;
            __syncwarp();
        }
    }
    __syncthreads();

    // --- logs + global writes, all 512 threads over 1600 values ---
    for (int i = tid; i < NT * NS; i += 512) {
        const float v  = sh_H[i];
        const float lg = logf(v);
        g_H[i] = v;
        g_h[i] = lg;
        out_hidden[i] = lg;
    }
}

// ---------------------------------------------------------------------------
// Kernel 2 (fused): chain-weight lse (tz==0 blocks only) + observed probs.
// out1[t,n] = log( sum_s exp(log_em[s,n]) * H[t,s] )   (chain softmax sums to 1)
// grid: (20 n-blocks, 5 t-chunks of 20)
// ---------------------------------------------------------------------------
__global__ void obs_kernel(const float* __restrict__ uem,
                           const float* __restrict__ ucw,
                           float* __restrict__ out1) {
    __shared__ float sH[20 * NS];
    __shared__ float sEl[NS];
    const int tid = threadIdx.x;
    const int t0  = blockIdx.y * 20;

    if (tid < NS) sEl[tid] = g_em_lse[tid];
    for (int i = tid; i < 20 * NS; i += blockDim.x) sH[i] = g_H[t0 * NS + i];
    __syncthreads();

    const int n = blockIdx.x * blockDim.x + tid;
    if (n >= NN) return;

    // chain-weight lse once (only the tz==0 t-chunk computes it)
    if (blockIdx.y == 0) {
        const float4 a = reinterpret_cast<const float4*>(ucw)[n * 2 + 0];
        const float4 b = reinterpret_cast<const float4*>(ucw)[n * 2 + 1];
        float m = fmaxf(fmaxf(fmaxf(a.x, a.y), fmaxf(a.z, a.w)),
                        fmaxf(fmaxf(b.x, b.y), fmaxf(b.z, b.w)));
        float s = expf(a.x - m) + expf(a.y - m) + expf(a.z - m) + expf(a.w - m)
                + expf(b.x - m) + expf(b.y - m) + expf(b.z - m) + expf(b.w - m);
        g_cw_lse[n] = m + logf(s);
    }

    float P[NS];
    #pragma unroll
    for (int s = 0; s < NS; s++) P[s] = expf(uem[s * NN + n] - sEl[s]);

    #pragma unroll 4
    for (int t = 0; t < 20; t++) {
        float a0 = 0.f, a1 = 0.f;
        #pragma unroll
        for (int s = 0; s < 8; s++) {
            a0 = fmaf(P[s],     sH[t * NS + s],     a0);
            a1 = fmaf(P[s + 8], sH[t * NS + s + 8], a1);
        }
        out1[(t0 + t) * NN + n] = logf(a0 + a1);
    }
}

// ---------------------------------------------------------------------------
// Kernel 3: the 256 MB broadcast writer (t-split x4, streaming stores).
// perm[t,s,c,n] = (em[s,n]-em_lse[s]) + (cw[n,c]-cw_lse[n]) + h[t,s]
// grid: (5 q-blocks, 128 (s,c) pairs, 4 t-chunks of 25), block 256
// ---------------------------------------------------------------------------
__global__ void perm_kernel(const float* __restrict__ uem,
                            const float* __restrict__ ucw,
                            float* __restrict__ outp) {
    __shared__ float sh[25];
    const int by = blockIdx.y;        // s*8 + c
    const int s  = by >> 3;
    const int c  = by & 7;
    const int t0 = blockIdx.z * 25;
    const int tid = threadIdx.x;

    if (tid < 25) sh[tid] = g_h[(t0 + tid) * NS + s];
    __syncthreads();

    const int q = blockIdx.x * blockDim.x + tid;   // float4 index in n-row
    if (q >= NN / 4) return;
    const int n0 = q * 4;

    const float4 em  = *reinterpret_cast<const float4*>(uem + s * NN + n0);
    const float4 cwl = *reinterpret_cast<const float4*>(g_cw_lse + n0);
    const float  el  = g_em_lse[s];

    float4 base;
    base.x = em.x - el + ucw[(n0 + 0) * NC + c] - cwl.x;
    base.y = em.y - el + ucw[(n0 + 1) * NC + c] - cwl.y;
    base.z = em.z - el + ucw[(n0 + 2) * NC + c] - cwl.z;
    base.w = em.w - el + ucw[(n0 + 3) * NC + c] - cwl.w;

    float* ptr = outp + (size_t)t0 * (NS * NC * NN) + (size_t)by * NN + n0;
    #pragma unroll 5
    for (int t = 0; t < 25; t++) {
        const float hv = sh[t];
        float4 v;
        v.x = base.x + hv; v.y = base.y + hv; v.z = base.z + hv; v.w = base.w + hv;
        __stcs(reinterpret_cast<float4*>(ptr), v);   // streaming: no L2 retention
        ptr += NS * NC * NN;                          // next t-plane
    }
}

// ---------------------------------------------------------------------------
// Launch
// ---------------------------------------------------------------------------
extern "C" void kernel_launch(void* const* d_in, const int* in_sizes, int n_in,
                              void* d_out, int out_size) {
    const float* usi = (const float*)d_in[0];   // (16,)
    const float* ucw = (const float*)d_in[1];   // (1,5000,8)
    const float* uem = (const float*)d_in[2];   // (16,5000)
    const float* utr = (const float*)d_in[3];   // (16,16)

    float* out = (float*)d_out;
    float* out1    = out;                                   // (100,5000)
    float* outperm = out + (size_t)NT * NN;                 // (100,16,8,5000)
    float* outhid  = outperm + (size_t)NT * NS * NC * NN;   // (100,16)

    prep_kernel<<<1, 512>>>(usi, uem, utr, outhid);
    obs_kernel<<<dim3((NN + 255) / 256, 5), 256>>>(uem, ucw, out1);
    perm_kernel<<<dim3((NN / 4 + 255) / 256, NS * NC, 4), 256>>>(uem, ucw, outperm);
}

// round 5
// speedup vs baseline: 1.6895x; 1.0220x over previous
#include <cuda_runtime.h>
#include <math.h>

#define NS 16      // states
#define NN 5000    // nodes
#define NC 8       // chains
#define NT 100     // iters

// Scratch (allocation-free rule: __device__ globals)
__device__ float g_h[NT * NS];      // log hidden state probs
__device__ float g_H[NT * NS];      // exp(log hidden state probs)
__device__ float g_em_lse[NS];      // per-state logsumexp over nodes
__device__ float g_cw_lse[NN];      // per-node logsumexp over chains

// ---------------------------------------------------------------------------
// Kernel 1: everything small, parallel across 37 blocks x 256 threads.
//   blocks 0..15  : em_lse[b]  (lse over 5000 nodes of emission row b)
//   block  16     : softmaxes + 100-step prob-space recursion + logs
//   blocks 17..36 : cw_lse (per-node lse over 8 chains)
// ---------------------------------------------------------------------------
__global__ void prep_kernel(const float* __restrict__ usi,
                            const float* __restrict__ ucw,
                            const float* __restrict__ uem,
                            const float* __restrict__ utr,
                            float* __restrict__ out_hidden) {
    const int bx  = blockIdx.x;
    const int tid = threadIdx.x;

    if (bx < NS) {
        // ---- emission-row logsumexp, 256-thread reduction ----
        __shared__ float red[8];
        const float* row = uem + bx * NN;
        const int lane = tid & 31, wid = tid >> 5;

        float m = -3.402823466e38f;
        for (int i = tid; i < NN; i += 256) m = fmaxf(m, row[i]);
        #pragma unroll
        for (int o = 16; o; o >>= 1) m = fmaxf(m, __shfl_xor_sync(0xffffffffu, m, o));
        if (lane == 0) red[wid] = m;
        __syncthreads();
        m = red[0];
        #pragma unroll
        for (int w = 1; w < 8; w++) m = fmaxf(m, red[w]);
        __syncthreads();

        float s = 0.f;
        for (int i = tid; i < NN; i += 256) s += __expf(row[i] - m);
        #pragma unroll
        for (int o = 16; o; o >>= 1) s += __shfl_xor_sync(0xffffffffu, s, o);
        if (lane == 0) red[wid] = s;
        __syncthreads();
        if (tid == 0) {
            s = red[0];
            #pragma unroll
            for (int w = 1; w < 8; w++) s += red[w];
            g_em_lse[bx] = m + __logf(s);
        }
        return;
    }

    if (bx > NS) {
        // ---- chain-weight lse: node n over 8 chains ----
        const int n = (bx - NS - 1) * 256 + tid;
        if (n >= NN) return;
        const float4 a = reinterpret_cast<const float4*>(ucw)[n * 2 + 0];
        const float4 b = reinterpret_cast<const float4*>(ucw)[n * 2 + 1];
        float m = fmaxf(fmaxf(fmaxf(a.x, a.y), fmaxf(a.z, a.w)),
                        fmaxf(fmaxf(b.x, b.y), fmaxf(b.z, b.w)));
        float s = __expf(a.x - m) + __expf(a.y - m) + __expf(a.z - m) + __expf(a.w - m)
                + __expf(b.x - m) + __expf(b.y - m) + __expf(b.z - m) + __expf(b.w - m);
        g_cw_lse[n] = m + __logf(s);
        return;
    }

    // ---- block 16: softmaxes + recursion ----
    __shared__ float sh_P[NS][NS + 1];   // transition probs, row-stochastic
    __shared__ float sh_H[NT * NS];      // prob-space hidden marginals

    const int lane = tid & 31;

    if (tid < NS) {
        // transition row softmax (prob space)
        float m = -3.402823466e38f;
        #pragma unroll
        for (int j = 0; j < NS; j++) m = fmaxf(m, utr[tid * NS + j]);
        float s = 0.f;
        float e[NS];
        #pragma unroll
        for (int j = 0; j < NS; j++) { e[j] = __expf(utr[tid * NS + j] - m); s += e[j]; }
        const float inv = 1.0f / s;
        #pragma unroll
        for (int j = 0; j < NS; j++) sh_P[tid][j] = e[j] * inv;
    }
    __syncthreads();

    if (tid < 32) {
        // warp 0: shuffle-based serial recursion, H kept in lane registers
        const int j = lane & (NS - 1);

        // initial state softmax, computed redundantly in every lane
        float m = -3.402823466e38f;
        #pragma unroll
        for (int k = 0; k < NS; k++) m = fmaxf(m, usi[k]);
        float s = 0.f;
        float e[NS];
        #pragma unroll
        for (int k = 0; k < NS; k++) { e[k] = __expf(usi[k] - m); s += e[k]; }
        float h = e[j] / s;                 // H_0[j]
        if (lane < NS) sh_H[j] = h;

        float Pc[NS];
        #pragma unroll
        for (int i = 0; i < NS; i++) Pc[i] = sh_P[i][j];

        for (int t = 1; t < NT; t++) {
            float a0 = 0.f, a1 = 0.f, a2 = 0.f, a3 = 0.f;
            #pragma unroll
            for (int i = 0; i < 4; i++) {
                a0 = fmaf(__shfl_sync(0xffffffffu, h, i +  0), Pc[i +  0], a0);
                a1 = fmaf(__shfl_sync(0xffffffffu, h, i +  4), Pc[i +  4], a1);
                a2 = fmaf(__shfl_sync(0xffffffffu, h, i +  8), Pc[i +  8], a2);
                a3 = fmaf(__shfl_sync(0xffffffffu, h, i + 12), Pc[i + 12], a3);
            }
            h = (a0 + a1) + (a2 + a3);
            if (lane < NS) sh_H[t * NS + j] = h;
        }
    }
    __syncthreads();

    // logs + global writes, 256 threads over 1600 values
    for (int i = tid; i < NT * NS; i += 256) {
        const float v  = sh_H[i];
        const float lg = __logf(v);
        g_H[i] = v;
        g_h[i] = lg;
        out_hidden[i] = lg;
    }
}

// ---------------------------------------------------------------------------
// Kernel 2: out1[t,n] = log( sum_s exp(log_em[s,n]) * H[t,s] )
// (chain softmax sums to 1 and drops out of the joint lse over (s,c))
// grid: (20 n-blocks, 5 t-chunks of 20)
// ---------------------------------------------------------------------------
__global__ void obs_kernel(const float* __restrict__ uem,
                           float* __restrict__ out1) {
    __shared__ float sH[20 * NS];
    __shared__ float sEl[NS];
    const int tid = threadIdx.x;
    const int t0  = blockIdx.y * 20;

    if (tid < NS) sEl[tid] = g_em_lse[tid];
    for (int i = tid; i < 20 * NS; i += blockDim.x) sH[i] = g_H[t0 * NS + i];
    __syncthreads();

    const int n = blockIdx.x * blockDim.x + tid;
    if (n >= NN) return;

    float P[NS];
    #pragma unroll
    for (int s = 0; s < NS; s++) P[s] = __expf(uem[s * NN + n] - sEl[s]);

    #pragma unroll 4
    for (int t = 0; t < 20; t++) {
        float a0 = 0.f, a1 = 0.f;
        #pragma unroll
        for (int s = 0; s < 8; s++) {
            a0 = fmaf(P[s],     sH[t * NS + s],     a0);
            a1 = fmaf(P[s + 8], sH[t * NS + s + 8], a1);
        }
        out1[(t0 + t) * NN + n] = __logf(a0 + a1);
    }
}

// ---------------------------------------------------------------------------
// Kernel 3: the 256 MB broadcast writer (t-split x4, streaming stores).
// perm[t,s,c,n] = (em[s,n]-em_lse[s]) + (cw[n,c]-cw_lse[n]) + h[t,s]
// grid: (5 q-blocks, 128 (s,c) pairs, 4 t-chunks of 25), block 256
// ---------------------------------------------------------------------------
__global__ void perm_kernel(const float* __restrict__ uem,
                            const float* __restrict__ ucw,
                            float* __restrict__ outp) {
    __shared__ float sh[25];
    const int by = blockIdx.y;        // s*8 + c
    const int s  = by >> 3;
    const int c  = by & 7;
    const int t0 = blockIdx.z * 25;
    const int tid = threadIdx.x;

    if (tid < 25) sh[tid] = g_h[(t0 + tid) * NS + s];
    __syncthreads();

    const int q = blockIdx.x * blockDim.x + tid;   // float4 index in n-row
    if (q >= NN / 4) return;
    const int n0 = q * 4;

    const float4 em  = *reinterpret_cast<const float4*>(uem + s * NN + n0);
    const float4 cwl = *reinterpret_cast<const float4*>(g_cw_lse + n0);
    const float  el  = g_em_lse[s];

    float4 base;
    base.x = em.x - el + ucw[(n0 + 0) * NC + c] - cwl.x;
    base.y = em.y - el + ucw[(n0 + 1) * NC + c] - cwl.y;
    base.z = em.z - el + ucw[(n0 + 2) * NC + c] - cwl.z;
    base.w = em.w - el + ucw[(n0 + 3) * NC + c] - cwl.w;

    float* ptr = outp + (size_t)t0 * (NS * NC * NN) + (size_t)by * NN + n0;
    #pragma unroll 5
    for (int t = 0; t < 25; t++) {
        const float hv = sh[t];
        float4 v;
        v.x = base.x + hv; v.y = base.y + hv; v.z = base.z + hv; v.w = base.w + hv;
        __stcs(reinterpret_cast<float4*>(ptr), v);   // streaming: no L2 retention
        ptr += NS * NC * NN;                          // next t-plane
    }
}

// ---------------------------------------------------------------------------
// Launch
// ---------------------------------------------------------------------------
extern "C" void kernel_launch(void* const* d_in, const int* in_sizes, int n_in,
                              void* d_out, int out_size) {
    const float* usi = (const float*)d_in[0];   // (16,)
    const float* ucw = (const float*)d_in[1];   // (1,5000,8)
    const float* uem = (const float*)d_in[2];   // (16,5000)
    const float* utr = (const float*)d_in[3];   // (16,16)

    float* out = (float*)d_out;
    float* out1    = out;                                   // (100,5000)
    float* outperm = out + (size_t)NT * NN;                 // (100,16,8,5000)
    float* outhid  = outperm + (size_t)NT * NS * NC * NN;   // (100,16)

    // 16 em_lse blocks + 1 recursion block + 20 cw_lse blocks
    prep_kernel<<<NS + 1 + 20, 256>>>(usi, ucw, uem, utr, outhid);
    obs_kernel<<<dim3((NN + 255) / 256, 5), 256>>>(uem, out1);
    perm_kernel<<<dim3((NN / 4 + 255) / 256, NS * NC, 4), 256>>>(uem, ucw, outperm);
}

// round 8
// speedup vs baseline: 2.1252x; 1.2579x over previous
#include <cuda_runtime.h>
#include <math.h>

#define NS 16      // states
#define NN 5000    // nodes
#define NC 8       // chains
#define NT 100     // iters
#define CHUNK 10   // recursion chunk length (10 chunks x 10 t-rows)

// Scratch (allocation-free rule: __device__ globals)
__device__ float g_h[NT * NS];      // log hidden state probs
__device__ float g_H[NT * NS];      // exp(log hidden state probs)
__device__ float g_em_lse[NS];      // per-state logsumexp over nodes
__device__ float g_cw_lse[NN];      // per-node logsumexp over chains

// ---------------------------------------------------------------------------
// Kernel 1: everything small, parallel across 37 blocks x 256 threads.
//   blocks 0..15  : em_lse[b]  (lse over 5000 nodes of emission row b, float4)
//   block  16     : softmaxes + chunked matrix-power recursion + logs
//   blocks 17..36 : cw_lse (per-node lse over 8 chains)
// ---------------------------------------------------------------------------
__global__ void prep_kernel(const float* __restrict__ usi,
                            const float* __restrict__ ucw,
                            const float* __restrict__ uem,
                            const float* __restrict__ utr,
                            float* __restrict__ out_hidden) {
    const int bx  = blockIdx.x;
    const int tid = threadIdx.x;

    if (bx < NS) {
        // ---- emission-row logsumexp, float4 + 256-thread reduction ----
        __shared__ float red[8];
        const float4* row4 = reinterpret_cast<const float4*>(uem + bx * NN);
        const int lane = tid & 31, wid = tid >> 5;

        float m = -3.402823466e38f;
        for (int i = tid; i < NN / 4; i += 256) {
            const float4 v = row4[i];
            m = fmaxf(m, fmaxf(fmaxf(v.x, v.y), fmaxf(v.z, v.w)));
        }
        #pragma unroll
        for (int o = 16; o; o >>= 1) m = fmaxf(m, __shfl_xor_sync(0xffffffffu, m, o));
        if (lane == 0) red[wid] = m;
        __syncthreads();
        m = red[0];
        #pragma unroll
        for (int w = 1; w < 8; w++) m = fmaxf(m, red[w]);
        __syncthreads();

        float s = 0.f;
        for (int i = tid; i < NN / 4; i += 256) {
            const float4 v = row4[i];
            s += __expf(v.x - m) + __expf(v.y - m) + __expf(v.z - m) + __expf(v.w - m);
        }
        #pragma unroll
        for (int o = 16; o; o >>= 1) s += __shfl_xor_sync(0xffffffffu, s, o);
        if (lane == 0) red[wid] = s;
        __syncthreads();
        if (tid == 0) {
            s = red[0];
            #pragma unroll
            for (int w = 1; w < 8; w++) s += red[w];
            g_em_lse[bx] = m + __logf(s);
        }
        return;
    }

    if (bx > NS) {
        // ---- chain-weight lse: node n over 8 chains ----
        const int n = (bx - NS - 1) * 256 + tid;
        if (n >= NN) return;
        const float4 a = reinterpret_cast<const float4*>(ucw)[n * 2 + 0];
        const float4 b = reinterpret_cast<const float4*>(ucw)[n * 2 + 1];
        float m = fmaxf(fmaxf(fmaxf(a.x, a.y), fmaxf(a.z, a.w)),
                        fmaxf(fmaxf(b.x, b.y), fmaxf(b.z, b.w)));
        float s = __expf(a.x - m) + __expf(a.y - m) + __expf(a.z - m) + __expf(a.w - m)
                + __expf(b.x - m) + __expf(b.y - m) + __expf(b.z - m) + __expf(b.w - m);
        g_cw_lse[n] = m + __logf(s);
        return;
    }

    // ======================= block 16: recursion =======================
    __shared__ float sh_P [NS][NS + 1];   // P (row-stochastic transition)
    __shared__ float sh_T1[NS][NS + 1];   // scratch: P^2, then P^8
    __shared__ float sh_T2[NS][NS + 1];   // scratch: P^4
    __shared__ float sh_Q [NS][NS + 1];   // Q = P^10
    __shared__ float sh_H [NT * NS];      // prob-space hidden marginals

    const int i16 = tid >> 4;             // 0..15
    const int j16 = tid & 15;             // 0..15

    // --- transition row softmax (prob space) + initial state softmax ---
    if (tid < NS) {
        float m = -3.402823466e38f;
        #pragma unroll
        for (int j = 0; j < NS; j++) m = fmaxf(m, utr[tid * NS + j]);
        float s = 0.f;
        float e[NS];
        #pragma unroll
        for (int j = 0; j < NS; j++) { e[j] = __expf(utr[tid * NS + j] - m); s += e[j]; }
        const float inv = 1.0f / s;
        #pragma unroll
        for (int j = 0; j < NS; j++) sh_P[tid][j] = e[j] * inv;
    }
    if (tid >= 32 && tid < 48) {          // separate warp: initial softmax
        const int j = tid - 32;
        float m = -3.402823466e38f;
        #pragma unroll
        for (int k = 0; k < NS; k++) m = fmaxf(m, usi[k]);
        float s = 0.f;
        float e[NS];
        #pragma unroll
        for (int k = 0; k < NS; k++) { e[k] = __expf(usi[k] - m); s += e[k]; }
        sh_H[j] = e[j] / s;
    }
    __syncthreads();

    // --- Q = P^10 via P^2, P^4, P^8, P^8*P^2 (256-thread 16x16 matmuls) ---
    {
        float acc;
        // T1 = P*P
        acc = 0.f;
        #pragma unroll
        for (int k = 0; k < NS; k++) acc = fmaf(sh_P[i16][k], sh_P[k][j16], acc);
        sh_T1[i16][j16] = acc;            // P^2
        __syncthreads();
        // T2 = T1*T1
        acc = 0.f;
        #pragma unroll
        for (int k = 0; k < NS; k++) acc = fmaf(sh_T1[i16][k], sh_T1[k][j16], acc);
        sh_T2[i16][j16] = acc;            // P^4
        __syncthreads();
        // Q(tmp in T2 slot): P^8 = T2*T2 -> store into sh_Q temporarily
        acc = 0.f;
        #pragma unroll
        for (int k = 0; k < NS; k++) acc = fmaf(sh_T2[i16][k], sh_T2[k][j16], acc);
        sh_Q[i16][j16] = acc;             // P^8
        __syncthreads();
        // Q = P^8 * P^2
        acc = 0.f;
        #pragma unroll
        for (int k = 0; k < NS; k++) acc = fmaf(sh_Q[i16][k], sh_T1[k][j16], acc);
        __syncthreads();
        sh_Q[i16][j16] = acc;             // P^10
        __syncthreads();
    }

    // --- chunk starting vectors: H_{10w} = H_{10(w-1)} * Q, w=1..9 (serial) ---
    if (tid < NS) {
        const int j = tid;
        float Qc[NS];
        #pragma unroll
        for (int i = 0; i < NS; i++) Qc[i] = sh_Q[i][j];
        for (int w = 1; w < NT / CHUNK; w++) {
            const float* hp = sh_H + (w - 1) * CHUNK * NS;
            float a0 = 0.f, a1 = 0.f, a2 = 0.f, a3 = 0.f;
            #pragma unroll
            for (int i = 0; i < 4; i++) {
                a0 = fmaf(hp[i +  0], Qc[i +  0], a0);
                a1 = fmaf(hp[i +  4], Qc[i +  4], a1);
                a2 = fmaf(hp[i +  8], Qc[i +  8], a2);
                a3 = fmaf(hp[i + 12], Qc[i + 12], a3);
            }
            __syncwarp(0xFFFFu);
            sh_H[w * CHUNK * NS + j] = (a0 + a1) + (a2 + a3);
            __syncwarp(0xFFFFu);
        }
    }
    __syncthreads();

    // --- parallel chunk expansion: 10 groups of 16 threads, 9 steps each ---
    if (tid < (NT / CHUNK) * NS) {        // tids 0..159 = warps 0..4 fully
        const int g = tid >> 4;           // chunk 0..9
        const int j = tid & 15;
        float Pc[NS];
        #pragma unroll
        for (int i = 0; i < NS; i++) Pc[i] = sh_P[i][j];

        const int t0 = g * CHUNK;
        for (int tl = 1; tl < CHUNK; tl++) {
            const float* hp = sh_H + (t0 + tl - 1) * NS;
            float a0 = 0.f, a1 = 0.f, a2 = 0.f, a3 = 0.f;
            #pragma unroll
            for (int i = 0; i < 4; i++) {
                a0 = fmaf(hp[i +  0], Pc[i +  0], a0);
                a1 = fmaf(hp[i +  4], Pc[i +  4], a1);
                a2 = fmaf(hp[i +  8], Pc[i +  8], a2);
                a3 = fmaf(hp[i + 12], Pc[i + 12], a3);
            }
            __syncwarp();                 // both 16-groups in a warp converge here
            sh_H[(t0 + tl) * NS + j] = (a0 + a1) + (a2 + a3);
            __syncwarp();
        }
    }
    __syncthreads();

    // --- logs + global writes, 256 threads over 1600 values ---
    for (int i = tid; i < NT * NS; i += 256) {
        const float v  = sh_H[i];
        const float lg = __logf(v);
        g_H[i] = v;
        g_h[i] = lg;
        out_hidden[i] = lg;
    }
}

// ---------------------------------------------------------------------------
// Kernel 2: out1[t,n] = log( sum_s exp(log_em[s,n]) * H[t,s] )
// (chain softmax sums to 1 and drops out of the joint lse over (s,c))
// grid: (20 n-blocks, 5 t-chunks of 20)
// ---------------------------------------------------------------------------
__global__ void obs_kernel(const float* __restrict__ uem,
                           float* __restrict__ out1) {
    __shared__ float sH[20 * NS];
    __shared__ float sEl[NS];
    const int tid = threadIdx.x;
    const int t0  = blockIdx.y * 20;

    if (tid < NS) sEl[tid] = g_em_lse[tid];
    for (int i = tid; i < 20 * NS; i += blockDim.x) sH[i] = g_H[t0 * NS + i];
    __syncthreads();

    const int n = blockIdx.x * blockDim.x + tid;
    if (n >= NN) return;

    float P[NS];
    #pragma unroll
    for (int s = 0; s < NS; s++) P[s] = __expf(uem[s * NN + n] - sEl[s]);

    #pragma unroll 4
    for (int t = 0; t < 20; t++) {
        float a0 = 0.f, a1 = 0.f;
        #pragma unroll
        for (int s = 0; s < 8; s++) {
            a0 = fmaf(P[s],     sH[t * NS + s],     a0);
            a1 = fmaf(P[s + 8], sH[t * NS + s + 8], a1);
        }
        out1[(t0 + t) * NN + n] = __logf(a0 + a1);
    }
}

// ---------------------------------------------------------------------------
// Kernel 3: the 256 MB broadcast writer (t-split x4, streaming stores).
// perm[t,s,c,n] = (em[s,n]-em_lse[s]) + (cw[n,c]-cw_lse[n]) + h[t,s]
// grid: (5 q-blocks, 128 (s,c) pairs, 4 t-chunks of 25), block 256
// ---------------------------------------------------------------------------
__global__ void perm_kernel(const float* __restrict__ uem,
                            const float* __restrict__ ucw,
                            float* __restrict__ outp) {
    __shared__ float sh[25];
    const int by = blockIdx.y;        // s*8 + c
    const int s  = by >> 3;
    const int c  = by & 7;
    const int t0 = blockIdx.z * 25;
    const int tid = threadIdx.x;

    if (tid < 25) sh[tid] = g_h[(t0 + tid) * NS + s];
    __syncthreads();

    const int q = blockIdx.x * blockDim.x + tid;   // float4 index in n-row
    if (q >= NN / 4) return;
    const int n0 = q * 4;

    const float4 em  = *reinterpret_cast<const float4*>(uem + s * NN + n0);
    const float4 cwl = *reinterpret_cast<const float4*>(g_cw_lse + n0);
    const float  el  = g_em_lse[s];

    float4 base;
    base.x = em.x - el + ucw[(n0 + 0) * NC + c] - cwl.x;
    base.y = em.y - el + ucw[(n0 + 1) * NC + c] - cwl.y;
    base.z = em.z - el + ucw[(n0 + 2) * NC + c] - cwl.z;
    base.w = em.w - el + ucw[(n0 + 3) * NC + c] - cwl.w;

    float* ptr = outp + (size_t)t0 * (NS * NC * NN) + (size_t)by * NN + n0;
    #pragma unroll 5
    for (int t = 0; t < 25; t++) {
        const float hv = sh[t];
        float4 v;
        v.x = base.x + hv; v.y = base.y + hv; v.z = base.z + hv; v.w = base.w + hv;
        __stcs(reinterpret_cast<float4*>(ptr), v);   // streaming: no L2 retention
        ptr += NS * NC * NN;                          // next t-plane
    }
}

// ---------------------------------------------------------------------------
// Launch
// ---------------------------------------------------------------------------
extern "C" void kernel_launch(void* const* d_in, const int* in_sizes, int n_in,
                              void* d_out, int out_size) {
    const float* usi = (const float*)d_in[0];   // (16,)
    const float* ucw = (const float*)d_in[1];   // (1,5000,8)
    const float* uem = (const float*)d_in[2];   // (16,5000)
    const float* utr = (const float*)d_in[3];   // (16,16)

    float* out = (float*)d_out;
    float* out1    = out;                                   // (100,5000)
    float* outperm = out + (size_t)NT * NN;                 // (100,16,8,5000)
    float* outhid  = outperm + (size_t)NT * NS * NC * NN;   // (100,16)

    // 16 em_lse blocks + 1 recursion block + 20 cw_lse blocks
    prep_kernel<<<NS + 1 + 20, 256>>>(usi, ucw, uem, utr, outhid);
    obs_kernel<<<dim3((NN + 255) / 256, 5), 256>>>(uem, out1);
    perm_kernel<<<dim3((NN / 4 + 255) / 256, NS * NC, 4), 256>>>(uem, ucw, outperm);
}